// round 16
// baseline (speedup 1.0000x reference)
#include <cuda_runtime.h>
#include <cuda_bf16.h>
#include <cstdint>

#define N 8192
#define D 256
#define BM 128
#define BN 128
#define NTILES 64
#define NBLOCKS (NTILES * (NTILES + 1) / 2)   // 2080 upper-triangular tiles

// ---- smem layout (bytes): 3 stages x (Ahi,Alo,Bhi,Blo) x 8KB ----
#define SM_STG   0
#define STG_SZ   32768
#define SM_HC    (3 * STG_SZ)
#define SM_SC    (SM_HC + 512)
#define SM_RED   (SM_SC + 512)         // 128*2 u64 = 2KB
#define SM_TOTAL (SM_RED + 2048)       // 101376 bytes -> occ 2 (202.8KB < 228KB)

// ---- device scratch (no allocation) ----
__device__ float g_sq[N];
__device__ __align__(16) uint32_t g_hi[N * (D / 2)];
__device__ __align__(16) uint32_t g_lo[N * (D / 2)];
__device__ unsigned long long g_key[N];

#define KEY_INF 0xFFFFFFFFFFFFFFFFull

// ============================ PTX helpers ============================
__device__ __forceinline__ uint32_t smem_to_u32(const void* p) {
    uint32_t a;
    asm("{ .reg .u64 t; cvta.to.shared.u64 t, %1; cvt.u32.u64 %0, t; }" : "=r"(a) : "l"(p));
    return a;
}
#define CP_ASYNC16(dst, src) \
    asm volatile("cp.async.cg.shared.global [%0], [%1], 16;" :: "r"(dst), "l"(src))
#define CP_COMMIT() asm volatile("cp.async.commit_group;" ::: "memory")
#define CP_WAIT0()  asm volatile("cp.async.wait_group 0;" ::: "memory")
#define CP_WAIT1()  asm volatile("cp.async.wait_group 1;" ::: "memory")

#define LDSM_X4(r, addr) \
    asm volatile("ldmatrix.sync.aligned.m8n8.x4.shared.b16 {%0,%1,%2,%3}, [%4];" \
        : "=r"((r)[0]), "=r"((r)[1]), "=r"((r)[2]), "=r"((r)[3]) : "r"(addr))

#define MMA16816(c, a, b0, b1) \
    asm("mma.sync.aligned.m16n8k16.row.col.f32.bf16.bf16.f32 " \
        "{%0,%1,%2,%3}, {%4,%5,%6,%7}, {%8,%9}, {%0,%1,%2,%3};" \
        : "+f"((c)[0]), "+f"((c)[1]), "+f"((c)[2]), "+f"((c)[3]) \
        : "r"((a)[0]), "r"((a)[1]), "r"((a)[2]), "r"((a)[3]), "r"(b0), "r"(b1))

__device__ __forceinline__ uint32_t swz(int r, int c16) {
    return (uint32_t)(r * 64 + ((c16 ^ ((r >> 1) & 3)) << 4));
}
__device__ __forceinline__ unsigned long long shfl_xor_u64(unsigned long long v, int m) {
    uint32_t lo = (uint32_t)v, hi = (uint32_t)(v >> 32);
    lo = __shfl_xor_sync(0xffffffffu, lo, m);
    hi = __shfl_xor_sync(0xffffffffu, hi, m);
    return ((unsigned long long)hi << 32) | lo;
}
__device__ __forceinline__ unsigned long long umin64(unsigned long long a, unsigned long long b) {
    return a < b ? a : b;
}

// ============================================================================
// Fused prep: copy e_actv & e_ap to output, split A -> bf16 hi/lo, row norms,
// init keys. 8 rows per 256-thread block (one warp per row). [best: 8.26us]
// ============================================================================
__global__ void prep_kernel(const float* __restrict__ A, const float* __restrict__ P,
                            float* __restrict__ out) {
    const size_t nd = (size_t)N * D;
    int gid = blockIdx.x * 256 + threadIdx.x;
    if (gid < N) g_key[gid] = KEY_INF;

    {
        const float4* src = (const float4*)(P + (size_t)blockIdx.x * 8 * D);
        float4*       dst = (float4*)(out + nd + (size_t)blockIdx.x * 8 * D);
        dst[threadIdx.x]       = src[threadIdx.x];
        dst[threadIdx.x + 256] = src[threadIdx.x + 256];
    }

    int row  = blockIdx.x * 8 + (threadIdx.x >> 5);
    int lane = threadIdx.x & 31;
    const float4* a  = (const float4*)(A + (size_t)row * D);
    float4*       oa = (float4*)(out + (size_t)row * D);
    float s = 0.f;
#pragma unroll
    for (int q = 0; q < 2; ++q) {
        float4 v = a[lane + 32 * q];
        oa[lane + 32 * q] = v;
        s += v.x * v.x + v.y * v.y + v.z * v.z + v.w * v.w;
        __nv_bfloat162 h0 = __floats2bfloat162_rn(v.x, v.y);
        __nv_bfloat162 h1 = __floats2bfloat162_rn(v.z, v.w);
        float lx = v.x - __bfloat162float(h0.x);
        float ly = v.y - __bfloat162float(h0.y);
        float lz = v.z - __bfloat162float(h1.x);
        float lw = v.w - __bfloat162float(h1.y);
        __nv_bfloat162 l0 = __floats2bfloat162_rn(lx, ly);
        __nv_bfloat162 l1 = __floats2bfloat162_rn(lz, lw);
        uint2 hv = make_uint2(*reinterpret_cast<uint32_t*>(&h0), *reinterpret_cast<uint32_t*>(&h1));
        uint2 lv = make_uint2(*reinterpret_cast<uint32_t*>(&l0), *reinterpret_cast<uint32_t*>(&l1));
        size_t w = (size_t)row * (D / 2) + (lane + 32 * q) * 2;
        *(uint2*)(g_hi + w) = hv;
        *(uint2*)(g_lo + w) = lv;
    }
#pragma unroll
    for (int o = 16; o; o >>= 1) s += __shfl_xor_sync(0xffffffffu, s, o);
    if (lane == 0) g_sq[row] = s;
}

// ============================================================================
// Symmetric bf16x3 Gram tiles (upper-triangular) + dual-direction argmin.
// 3-stage cp.async pipeline, ONE __syncthreads per k-chunk (fully unrolled).
// [R10-certified structure]
// ============================================================================
__global__ __launch_bounds__(256, 2) void argmin_mma_kernel(const int* __restrict__ host) {
    extern __shared__ char smem[];
    const uint32_t sb  = smem_to_u32(smem);
    int*   hc  = (int*)(smem + SM_HC);
    float* sc  = (float*)(smem + SM_SC);
    unsigned long long* red = (unsigned long long*)(smem + SM_RED);

    const int tid  = threadIdx.x;
    const int lane = tid & 31;
    const int wid  = tid >> 5;
    const int warp_m = wid & 3;
    const int warp_n = wid >> 2;

    // ---- triangular tile decode: bid -> (ti, tj), tj >= ti ----
    const int bid = blockIdx.x;
    int ti = (int)(64.5f - sqrtf(64.5f * 64.5f - 2.0f * (float)bid));
    while (ti > 0  && (ti * 64 - ti * (ti - 1) / 2) > bid) --ti;
    while (((ti + 1) * 64 - (ti + 1) * ti / 2) <= bid) ++ti;
    const int tj = ti + (bid - (ti * 64 - ti * (ti - 1) / 2));
    const int row_base = ti * BM;
    const int col_base = tj * BM;

    auto load_chunk = [&](int kc, int st) {
        const uint32_t stg = sb + SM_STG + st * STG_SZ;
#pragma unroll
        for (int hl = 0; hl < 2; ++hl) {
            const uint32_t* sbase = hl ? g_lo : g_hi;
#pragma unroll
            for (int it = 0; it < 2; ++it) {
                int idx = it * 256 + tid;
                int r = idx >> 2, c = idx & 3;
                uint32_t sw = swz(r, c);
                const uint32_t* srcA = sbase + (size_t)(row_base + r) * (D / 2) + kc * 16 + c * 4;
                const uint32_t* srcB = sbase + (size_t)(col_base + r) * (D / 2) + kc * 16 + c * 4;
                CP_ASYNC16(stg + hl * 8192 + sw, srcA);
                CP_ASYNC16(stg + 16384 + hl * 8192 + sw, srcB);
            }
        }
    };

    // issue loads FIRST (don't queue behind metadata LDGs)
    load_chunk(0, 0); CP_COMMIT();
    load_chunk(1, 1); CP_COMMIT();

    if (tid < 128) {
        hc[tid] = host[col_base + tid];
        sc[tid] = g_sq[col_base + tid];
    }

    float acc[2][8][4];
#pragma unroll
    for (int mt = 0; mt < 2; ++mt)
#pragma unroll
        for (int nt = 0; nt < 8; ++nt)
#pragma unroll
            for (int e = 0; e < 4; ++e) acc[mt][nt][e] = 0.f;

    const int a_roff = warp_m * 32 + (lane & 7) + ((lane >> 3) & 1) * 8;
    const int a_koff = (lane >> 4);
    const int b_roff = warp_n * 64 + (lane & 7) + (lane >> 4) * 8;
    const int b_koff = ((lane >> 3) & 1);

#pragma unroll
    for (int kc = 0; kc < 8; ++kc) {
        if (kc < 7) CP_WAIT1(); else CP_WAIT0();
        __syncthreads();   // publishes chunk kc; guards stage reuse; (kc=0) covers hc/sc init

        if (kc + 2 < 8) {
            load_chunk(kc + 2, (kc + 2) % 3);
            CP_COMMIT();
        }

        const uint32_t stg = sb + SM_STG + (kc % 3) * STG_SZ;
        const uint32_t aHi = stg, aLo = stg + 8192;
        const uint32_t bHi = stg + 16384, bLo = stg + 24576;

#pragma unroll
        for (int ks = 0; ks < 2; ++ks) {
            uint32_t ah[2][4], al[2][4];
#pragma unroll
            for (int mt = 0; mt < 2; ++mt) {
                uint32_t off = swz(a_roff + mt * 16, 2 * ks + a_koff);
                LDSM_X4(ah[mt], aHi + off);
                LDSM_X4(al[mt], aLo + off);
            }
            uint32_t b0[16], b1[16];
#pragma unroll
            for (int p = 0; p < 4; ++p)
                LDSM_X4(&b0[p * 4], bHi + swz(b_roff + p * 16, 2 * ks + b_koff));
            // pass 1: hi*hi
#pragma unroll
            for (int mt = 0; mt < 2; ++mt)
#pragma unroll
                for (int nt = 0; nt < 8; ++nt) {
                    const int bi = (nt >> 1) * 4 + (nt & 1) * 2;
                    MMA16816(acc[mt][nt], ah[mt], b0[bi], b0[bi + 1]);
                }
#pragma unroll
            for (int p = 0; p < 4; ++p)
                LDSM_X4(&b1[p * 4], bLo + swz(b_roff + p * 16, 2 * ks + b_koff));
            // pass 2: lo*hi
#pragma unroll
            for (int mt = 0; mt < 2; ++mt)
#pragma unroll
                for (int nt = 0; nt < 8; ++nt) {
                    const int bi = (nt >> 1) * 4 + (nt & 1) * 2;
                    MMA16816(acc[mt][nt], al[mt], b0[bi], b0[bi + 1]);
                }
            // pass 3: hi*lo
#pragma unroll
            for (int mt = 0; mt < 2; ++mt)
#pragma unroll
                for (int nt = 0; nt < 8; ++nt) {
                    const int bi = (nt >> 1) * 4 + (nt & 1) * 2;
                    MMA16816(acc[mt][nt], ah[mt], b1[bi], b1[bi + 1]);
                }
        }
    }
    __syncthreads();   // all compute done before epilogue uses red[]

    // ======================= epilogue: both directions =======================
    int   hr[2][2];
    float sr[2][2];
#pragma unroll
    for (int mt = 0; mt < 2; ++mt)
#pragma unroll
        for (int h = 0; h < 2; ++h) {
            int r = row_base + warp_m * 32 + mt * 16 + h * 8 + (lane >> 2);
            hr[mt][h] = host[r];
            sr[mt][h] = g_sq[r];
        }

    // --- row direction ---
#pragma unroll
    for (int mt = 0; mt < 2; ++mt)
#pragma unroll
        for (int h = 0; h < 2; ++h) {
            unsigned long long key = KEY_INF;
            const int   hrow = hr[mt][h];
            const float srow = sr[mt][h];
#pragma unroll
            for (int nt = 0; nt < 8; ++nt)
#pragma unroll
                for (int e = 0; e < 2; ++e) {
                    const int cl = warp_n * 64 + nt * 8 + (lane & 3) * 2 + e;
                    float d2 = fmaxf(fmaf(-2.0f, acc[mt][nt][h * 2 + e], srow + sc[cl]), 0.0f);
                    if (hc[cl] != hrow) {
                        unsigned long long k =
                            ((unsigned long long)__float_as_uint(d2) << 32) |
                            (unsigned int)(col_base + cl);
                        key = umin64(key, k);
                    }
                }
            key = umin64(key, shfl_xor_u64(key, 1));
            key = umin64(key, shfl_xor_u64(key, 2));
            if ((lane & 3) == 0) {
                int rl = warp_m * 32 + mt * 16 + h * 8 + (lane >> 2);
                red[rl * 2 + warp_n] = key;
            }
        }
    __syncthreads();
    if (tid < 128) {
        unsigned long long k = umin64(red[tid * 2], red[tid * 2 + 1]);
        if (k != KEY_INF) atomicMin(&g_key[row_base + tid], k);
    }

    // --- col direction (skip on diagonal tiles: exact duplicate of row dir) ---
    if (ti != tj) {
#pragma unroll
        for (int nt = 0; nt < 8; ++nt)
#pragma unroll
            for (int e = 0; e < 2; ++e) {
                const int cl = warp_n * 64 + nt * 8 + (lane & 3) * 2 + e;
                const int   hcol = hc[cl];
                const float scol = sc[cl];
                unsigned long long key = KEY_INF;
#pragma unroll
                for (int mt = 0; mt < 2; ++mt)
#pragma unroll
                    for (int h = 0; h < 2; ++h) {
                        float d2 = fmaxf(fmaf(-2.0f, acc[mt][nt][h * 2 + e], sr[mt][h] + scol), 0.0f);
                        if (hr[mt][h] != hcol) {
                            int r = row_base + warp_m * 32 + mt * 16 + h * 8 + (lane >> 2);
                            unsigned long long k =
                                ((unsigned long long)__float_as_uint(d2) << 32) | (unsigned int)r;
                            key = umin64(key, k);
                        }
                    }
                key = umin64(key, shfl_xor_u64(key, 4));
                key = umin64(key, shfl_xor_u64(key, 8));
                key = umin64(key, shfl_xor_u64(key, 16));
                if ((lane >> 2) == 0 && key != KEY_INF)
                    atomicMin(&g_key[col_base + cl], key);
            }
    }
}

// ============================================================================
// Finalize: gather e_actv[idx]; 16 rows per 1024-thread block. [best shape]
// ============================================================================
__global__ __launch_bounds__(1024) void finalize_kernel(const float* __restrict__ A,
                                                        float* __restrict__ out_an) {
    const int row = blockIdx.x * 16 + (threadIdx.x >> 6);
    const int t   = threadIdx.x & 63;
    const int idx = (int)(__ldg(&g_key[row]) & 0xFFFFFFFFu);
    const float4* src = (const float4*)(A + (size_t)idx * D);
    float4* dst = (float4*)(out_an + (size_t)row * D);
    dst[t] = src[t];
}

// ============================================================================
extern "C" void kernel_launch(void* const* d_in, const int* in_sizes, int n_in,
                              void* d_out, int out_size) {
    const float* e_actv = (const float*)d_in[0];
    const float* e_ap   = (const float*)d_in[1];
    const int*   host   = (const int*)d_in[2];
    float* out = (float*)d_out;
    const size_t nd = (size_t)N * D;

    cudaFuncSetAttribute(argmin_mma_kernel, cudaFuncAttributeMaxDynamicSharedMemorySize, SM_TOTAL);

    prep_kernel<<<N / 8, 256>>>(e_actv, e_ap, out);
    argmin_mma_kernel<<<NBLOCKS, 256, SM_TOTAL>>>(host);
    finalize_kernel<<<N / 16, 1024>>>(e_actv, out + 2 * nd);
}